// round 2
// baseline (speedup 1.0000x reference)
#include <cuda_runtime.h>
#include <cstdint>

#define HW    512
#define NPIX  (HW * HW)          // 262144
#define NC    64

// Scratch (allocation-free rule: __device__ globals)
__device__ float g_refT[(size_t)NPIX * NC];    // ref transposed to (pix, C)
__device__ float g_guideT[(size_t)NPIX * NC];  // accumulator (pix, C)
__device__ float g_weight[NPIX];

// ---------------------------------------------------------------------------
// 1) Transpose ref (C, H, W) -> refT (H*W, C). 64x64 tiles via smem.
// ---------------------------------------------------------------------------
__global__ __launch_bounds__(256) void transpose_ref_kernel(const float* __restrict__ ref) {
    __shared__ float tile[64][65];
    const int pixBase = blockIdx.x * 64;
    const int tx = threadIdx.x;   // 0..63
    const int ty = threadIdx.y;   // 0..3

    #pragma unroll
    for (int c = ty; c < NC; c += 4)
        tile[c][tx] = ref[(size_t)c * NPIX + pixBase + tx];   // coalesced over pixels
    __syncthreads();
    #pragma unroll
    for (int p = ty; p < 64; p += 4)
        g_refT[(size_t)(pixBase + p) * NC + tx] = tile[tx][p]; // coalesced over channels
}

// ---------------------------------------------------------------------------
// 2) Pass 1 as a GATHER: one warp per output pixel, float2 per lane (64 ch).
//    Writes guideT and weight (full init, no memset needed).
// ---------------------------------------------------------------------------
__global__ __launch_bounds__(256) void pass1_gather_kernel(const int* __restrict__ nnf_sr) {
    const int warp = (blockIdx.x * blockDim.x + threadIdx.x) >> 5;
    const int lane = threadIdx.x & 31;
    if (warp >= NPIX) return;
    const int ty = warp >> 9;
    const int tx = warp & (HW - 1);

    const float ws = 1.0f / (float)NPIX;
    float2 acc = make_float2(0.f, 0.f);
    int cnt = 0;

    #pragma unroll
    for (int dy = -1; dy <= 1; dy++) {
        #pragma unroll
        for (int dx = -1; dx <= 1; dx++) {
            const int sy = ty - dy, sx = tx - dx;
            if ((unsigned)sy < HW && (unsigned)sx < HW) {
                const int sidx = sy * HW + sx;
                const int ry = __ldg(&nnf_sr[2 * sidx]);
                const int rx = __ldg(&nnf_sr[2 * sidx + 1]);
                const int qy = ry + dy, qx = rx + dx;
                if ((unsigned)qy < HW && (unsigned)qx < HW) {
                    const float2* row =
                        (const float2*)(g_refT + (size_t)(qy * HW + qx) * NC);
                    const float2 v = __ldg(&row[lane]);
                    acc.x += v.x; acc.y += v.y;
                    cnt++;
                }
            }
        }
    }

    acc.x *= ws; acc.y *= ws;
    ((float2*)(g_guideT + (size_t)warp * NC))[lane] = acc;
    if (lane == 0) g_weight[warp] = ws * (float)cnt;
}

// ---------------------------------------------------------------------------
// 3) Pass 2 SCATTER: one warp per ref pixel. Reads refT (sliding window,
//    coalesced, L1/L2-hot), scatters with vector red.global.add.v2.f32.
// ---------------------------------------------------------------------------
__global__ __launch_bounds__(256) void pass2_scatter_kernel(const int* __restrict__ nnf_rs) {
    const int warp = (blockIdx.x * blockDim.x + threadIdx.x) >> 5;
    const int lane = threadIdx.x & 31;
    if (warp >= NPIX) return;
    const int ry = warp >> 9;
    const int rx = warp & (HW - 1);

    const int sy = __ldg(&nnf_rs[2 * warp]);
    const int sx = __ldg(&nnf_rs[2 * warp + 1]);
    const float wr = 2.0f / (float)NPIX;

    #pragma unroll
    for (int dy = -1; dy <= 1; dy++) {
        #pragma unroll
        for (int dx = -1; dx <= 1; dx++) {
            const int tyy = sy + dy, txx = sx + dx;
            const int qy = ry + dy, qx = rx + dx;
            if ((unsigned)tyy < HW && (unsigned)txx < HW &&
                (unsigned)qy  < HW && (unsigned)qx  < HW) {
                const float2 v = __ldg(
                    &((const float2*)(g_refT + (size_t)(qy * HW + qx) * NC))[lane]);
                float* dst = g_guideT + (size_t)(tyy * HW + txx) * NC + lane * 2;
                asm volatile("red.global.add.v2.f32 [%0], {%1, %2};"
                             :: "l"(dst), "f"(v.x * wr), "f"(v.y * wr) : "memory");
                if (lane == 0)
                    atomicAdd(&g_weight[tyy * HW + txx], wr);
            }
        }
    }
}

// ---------------------------------------------------------------------------
// 4) Normalize + transpose back: out (C, H, W) = guideT / weight.
// ---------------------------------------------------------------------------
__global__ __launch_bounds__(256) void normalize_kernel(float* __restrict__ out) {
    __shared__ float tile[64][65];
    __shared__ float invw[64];
    const int pixBase = blockIdx.x * 64;
    const int tx = threadIdx.x;   // 0..63
    const int ty = threadIdx.y;   // 0..3

    if (ty == 0) {
        const float w = g_weight[pixBase + tx];
        invw[tx] = (w == 0.f) ? 1.f : (1.f / w);
    }
    #pragma unroll
    for (int p = ty; p < 64; p += 4)
        tile[p][tx] = g_guideT[(size_t)(pixBase + p) * NC + tx];  // coalesced over C
    __syncthreads();
    #pragma unroll
    for (int c = ty; c < NC; c += 4)
        out[(size_t)c * NPIX + pixBase + tx] = tile[tx][c] * invw[tx]; // coalesced over pix
}

// ---------------------------------------------------------------------------
extern "C" void kernel_launch(void* const* d_in, const int* in_sizes, int n_in,
                              void* d_out, int out_size) {
    const float* ref    = (const float*)d_in[0];
    const int*   nnf_sr = (const int*)d_in[1];
    const int*   nnf_rs = (const int*)d_in[2];
    float*       out    = (float*)d_out;

    dim3 t2d(64, 4);
    transpose_ref_kernel<<<NPIX / 64, t2d>>>(ref);
    pass1_gather_kernel<<<NPIX / 8, 256>>>(nnf_sr);
    pass2_scatter_kernel<<<NPIX / 8, 256>>>(nnf_rs);
    normalize_kernel<<<NPIX / 64, t2d>>>(out);
}